// round 5
// baseline (speedup 1.0000x reference)
#include <cuda_runtime.h>
#include <cstdint>

// x: [65536, 512] fp32 in [0,1) -> out: [65536, 1536] fp32, 3 bit-planes MSB-first of
// q = round_half_even(x*8 - 0.5).
//
// R3: smem staging got DRAM to 71.6% but burned L1 (57%) on STS/LDS + BAR latency.
// R4/R5: pure shuffle transpose. Each lane packs its 12 output bits; output uint4 o of
// the warp's 96 takes nibble (m[o/3] >> 4*(o%3)) — single-source-lane, one shuffle each.
// LDG and STG both perfectly warp-coalesced; no smem, no barrier.

constexpr int THREADS = 256;
constexpr unsigned FULL = 0xFFFFFFFFu;

__device__ __forceinline__ unsigned pack12(float4 v) {
    float xs[4] = {v.x, v.y, v.z, v.w};
    unsigned m = 0;
#pragma unroll
    for (int j = 0; j < 4; j++) {
        // x*8 exact in fp32 (pow2) -> single-rounding fma == reference; _rn = half-to-even.
        int q = __float2int_rn(fmaf(xs[j], 8.0f, -0.5f));
        // stream bit 3j+0 = MSB ((q>>2)&1), 3j+1 = (q>>1)&1, 3j+2 = q&1
        unsigned rev3 = ((q >> 2) & 1) | (((q >> 1) & 1) << 1) | ((q & 1) << 2);
        m |= rev3 << (3 * j);
    }
    return m;
}

__device__ __forceinline__ uint4 expand_nib(unsigned nib) {
    // bit -> fp32 1.0f/0.0f without I2F: -(bit) & 0x3F800000
    return make_uint4((unsigned)(-(int)(nib & 1)) & 0x3F800000u,
                      (unsigned)(-(int)((nib >> 1) & 1)) & 0x3F800000u,
                      (unsigned)(-(int)((nib >> 2) & 1)) & 0x3F800000u,
                      (unsigned)(-(int)((nib >> 3) & 1)) & 0x3F800000u);
}

__global__ void __launch_bounds__(THREADS) quant_bits_kernel(
    const float4* __restrict__ in, uint4* __restrict__ out, int n4) {
    int lane = threadIdx.x & 31;
    int warp_global = blockIdx.x * (THREADS / 32) + (threadIdx.x >> 5);
    size_t in_base = (size_t)warp_global * 64;   // warp handles 64 consecutive float4s

    if (in_base + 64 <= (size_t)n4) {
        // Front-batched independent loads (MLP=2 per lane)
        float4 v0 = in[in_base + lane];
        float4 v1 = in[in_base + 32 + lane];
        unsigned m0 = pack12(v0);
        unsigned m1 = pack12(v1);

        size_t out_base = in_base * 3;           // 192 uint4s per warp
#pragma unroll
        for (int k = 0; k < 3; k++) {
            int o = k * 32 + lane;
            unsigned nib = (__shfl_sync(FULL, m0, o / 3) >> (4 * (o % 3))) & 0xFu;
            out[out_base + o] = expand_nib(nib);
        }
#pragma unroll
        for (int k = 0; k < 3; k++) {
            int o = k * 32 + lane;
            unsigned nib = (__shfl_sync(FULL, m1, o / 3) >> (4 * (o % 3))) & 0xFu;
            out[out_base + 96 + o] = expand_nib(nib);
        }
    } else {
        // Tail (not hit for n4 = 2^23, kept for safety): scalar per-element path.
        for (int t = 0; t < 2; t++) {
            size_t i = in_base + t * 32 + lane;
            if (i >= (size_t)n4) continue;
            float4 v = in[i];
            float xs[4] = {v.x, v.y, v.z, v.w};
            unsigned b[12];
#pragma unroll
            for (int j = 0; j < 4; j++) {
                int q = __float2int_rn(fmaf(xs[j], 8.0f, -0.5f));
                b[j * 3 + 0] = (unsigned)(-((q >> 2) & 1)) & 0x3F800000u;
                b[j * 3 + 1] = (unsigned)(-((q >> 1) & 1)) & 0x3F800000u;
                b[j * 3 + 2] = (unsigned)(-(q & 1)) & 0x3F800000u;
            }
            uint4* o = out + i * 3;
            o[0] = make_uint4(b[0], b[1], b[2], b[3]);
            o[1] = make_uint4(b[4], b[5], b[6], b[7]);
            o[2] = make_uint4(b[8], b[9], b[10], b[11]);
        }
    }
}

extern "C" void kernel_launch(void* const* d_in, const int* in_sizes, int n_in,
                              void* d_out, int out_size) {
    const float4* in = (const float4*)d_in[0];
    uint4* out = (uint4*)d_out;
    int n = in_sizes[0];   // 2^25 elements
    int n4 = n >> 2;       // 2^23 float4s
    int f4_per_block = (THREADS / 32) * 64;                 // 512
    int blocks = (n4 + f4_per_block - 1) / f4_per_block;    // 16384
    quant_bits_kernel<<<blocks, THREADS>>>(in, out, n4);
}